// round 1
// baseline (speedup 1.0000x reference)
#include <cuda_runtime.h>

#define B_SZ   4
#define S_LEN  2048
#define NH     16
#define HD     64
#define MODEL  1024
#define M_ROWS (B_SZ * S_LEN)                 // 8192
#define QKV_ELEMS (B_SZ * NH * S_LEN * HD)    // 8388608

// scratch: q, k, v in [B,H,S,D]; ao in [B,S,H*D]
__device__ float g_scratch[4ull * QKV_ELEMS];

// ---------------------------------------------------------------------------
// SGEMM: C = A @ W^T + bias.  A:[M,K] row-major, W:[N,K] row-major.
// mode 0: scatter into [B,H,S,D]  (projection epilogue)
// mode 1: plain row-major [M,N]   (final output)
// 128x128 tile, BK=8, 256 threads, 8x8 per-thread fragment.
// ---------------------------------------------------------------------------
__global__ __launch_bounds__(256) void sgemm_bias_kernel(
    const float* __restrict__ A, const float* __restrict__ W,
    const float* __restrict__ bias, float* __restrict__ C,
    int Kdim, int N, int mode)
{
    __shared__ float As[8][128];
    __shared__ float Bs[8][128];

    const int tid  = threadIdx.x;
    const int tx   = tid & 15;
    const int ty   = tid >> 4;
    const int row0 = blockIdx.y * 128;
    const int col0 = blockIdx.x * 128;
    const int lr   = tid >> 1;          // 0..127
    const int lk   = (tid & 1) << 2;    // 0 or 4

    const float* Ap = A + (size_t)(row0 + lr) * Kdim + lk;
    const float* Wp = W + (size_t)(col0 + lr) * Kdim + lk;

    float acc[8][8];
    #pragma unroll
    for (int i = 0; i < 8; i++)
        #pragma unroll
        for (int j = 0; j < 8; j++)
            acc[i][j] = 0.0f;

    float4 av = *(const float4*)(Ap);
    float4 wv = *(const float4*)(Wp);

    for (int k0 = 0; k0 < Kdim; k0 += 8) {
        As[lk + 0][lr] = av.x; As[lk + 1][lr] = av.y;
        As[lk + 2][lr] = av.z; As[lk + 3][lr] = av.w;
        Bs[lk + 0][lr] = wv.x; Bs[lk + 1][lr] = wv.y;
        Bs[lk + 2][lr] = wv.z; Bs[lk + 3][lr] = wv.w;
        __syncthreads();

        if (k0 + 8 < Kdim) {   // prefetch next tile while computing
            av = *(const float4*)(Ap + k0 + 8);
            wv = *(const float4*)(Wp + k0 + 8);
        }

        #pragma unroll
        for (int kk = 0; kk < 8; kk++) {
            float a[8], b[8];
            *(float4*)(&a[0]) = *(const float4*)(&As[kk][ty * 8]);
            *(float4*)(&a[4]) = *(const float4*)(&As[kk][ty * 8 + 4]);
            *(float4*)(&b[0]) = *(const float4*)(&Bs[kk][tx * 8]);
            *(float4*)(&b[4]) = *(const float4*)(&Bs[kk][tx * 8 + 4]);
            #pragma unroll
            for (int i = 0; i < 8; i++)
                #pragma unroll
                for (int j = 0; j < 8; j++)
                    acc[i][j] = fmaf(a[i], b[j], acc[i][j]);
        }
        __syncthreads();
    }

    #pragma unroll
    for (int i = 0; i < 8; i++) {
        const int m = row0 + ty * 8 + i;
        #pragma unroll
        for (int j = 0; j < 8; j++) {
            const int n = col0 + tx * 8 + j;
            const float v = acc[i][j] + bias[n];
            if (mode == 0) {
                const int b  = m >> 11;        // /S_LEN
                const int s  = m & (S_LEN - 1);
                const int hh = n >> 6;         // /HD
                const int d  = n & (HD - 1);
                C[(((size_t)(b * NH + hh) * S_LEN) + s) * HD + d] = v;
            } else {
                C[(size_t)m * N + n] = v;
            }
        }
    }
}

// ---------------------------------------------------------------------------
// Flash attention with bidirectional ALiBi. One block = 64 queries of one
// (b,h). Heads 0..7 causal (visit kv tiles 0..qtile), heads 8..15 anti-causal
// (visit kv tiles qtile..31). Online softmax, fp32.
// Dynamic smem: Qs^T[64][68], Ks^T[64][68], Vs[64][68], Ss[64][68] + stats.
// ---------------------------------------------------------------------------
#define APAD 68
#define ATTN_SMEM ((4 * 64 * APAD + 128) * 4)

__global__ __launch_bounds__(256) void attn_kernel(
    const float* __restrict__ Q, const float* __restrict__ K,
    const float* __restrict__ V, float* __restrict__ AO)
{
    extern __shared__ float sm[];
    float* Qs = sm;                    // [d][i] transposed
    float* Ks = Qs + 64 * APAD;        // [d][j] transposed
    float* Vs = Ks + 64 * APAD;        // [j][d] natural
    float* Ss = Vs + 64 * APAD;        // [i][j] natural
    float* corr_s = Ss + 64 * APAD;    // [64]
    float* l_s    = corr_s + 64;       // [64]

    const int tid = threadIdx.x;
    const int tx  = tid & 15;
    const int ty  = tid >> 4;
    const int qtile = blockIdx.x;
    const int bh    = blockIdx.y;
    const int h     = bh & (NH - 1);
    const int q0    = qtile * 64;
    const bool fwd  = (h < 8);
    const int sidx  = fwd ? h : (h - 8);
    // slope = 24^{-(sidx+1)/8} = 2^{-(sidx+1)*log2(24)/8}
    const float slope = exp2f(-(float)(sidx + 1) * 0.57312031259014454f);
    const float scale = 0.125f;   // 1/sqrt(64)

    const float* Qb = Q + (size_t)bh * S_LEN * HD;
    const float* Kb = K + (size_t)bh * S_LEN * HD;
    const float* Vb = V + (size_t)bh * S_LEN * HD;

    // load Q tile transposed [d][i]
    #pragma unroll
    for (int it = 0; it < 4; it++) {
        int idx = tid + it * 256;
        int row = idx >> 4;
        int g4  = (idx & 15) << 2;
        float4 v = *(const float4*)(Qb + (size_t)(q0 + row) * HD + g4);
        Qs[(g4 + 0) * APAD + row] = v.x;
        Qs[(g4 + 1) * APAD + row] = v.y;
        Qs[(g4 + 2) * APAD + row] = v.z;
        Qs[(g4 + 3) * APAD + row] = v.w;
    }

    float o[4][4];
    #pragma unroll
    for (int i = 0; i < 4; i++)
        #pragma unroll
        for (int j = 0; j < 4; j++)
            o[i][j] = 0.0f;

    // per-row softmax state (threads tid>>2 own row r; 4 threads/row redundant)
    float m_run = -3.0e38f, l_run = 0.0f;
    const int r  = tid >> 2;
    const int c0 = (tid & 3) * 16;
    const int qi = q0 + r;

    const int kt_begin = fwd ? 0 : qtile;
    const int kt_end   = fwd ? qtile : (S_LEN / 64 - 1);

    for (int kt = kt_begin; kt <= kt_end; kt++) {
        const int k0 = kt * 64;
        __syncthreads();  // prior PV must finish before overwriting tiles

        #pragma unroll
        for (int it = 0; it < 4; it++) {
            int idx = tid + it * 256;
            int row = idx >> 4;
            int g4  = (idx & 15) << 2;
            float4 kv = *(const float4*)(Kb + (size_t)(k0 + row) * HD + g4);
            Ks[(g4 + 0) * APAD + row] = kv.x;
            Ks[(g4 + 1) * APAD + row] = kv.y;
            Ks[(g4 + 2) * APAD + row] = kv.z;
            Ks[(g4 + 3) * APAD + row] = kv.w;
            float4 vv = *(const float4*)(Vb + (size_t)(k0 + row) * HD + g4);
            *(float4*)(&Vs[row * APAD + g4]) = vv;
        }
        __syncthreads();

        // scores S = Q K^T  (thread -> rows 4ty.., cols 4tx..)
        float sacc[4][4];
        #pragma unroll
        for (int i = 0; i < 4; i++)
            #pragma unroll
            for (int j = 0; j < 4; j++)
                sacc[i][j] = 0.0f;

        #pragma unroll 16
        for (int d = 0; d < 64; d++) {
            float4 qa = *(const float4*)(&Qs[d * APAD + 4 * ty]);
            float4 kb = *(const float4*)(&Ks[d * APAD + 4 * tx]);
            float a0 = qa.x, a1 = qa.y, a2 = qa.z, a3 = qa.w;
            float b0 = kb.x, b1 = kb.y, b2 = kb.z, b3 = kb.w;
            sacc[0][0] = fmaf(a0, b0, sacc[0][0]); sacc[0][1] = fmaf(a0, b1, sacc[0][1]);
            sacc[0][2] = fmaf(a0, b2, sacc[0][2]); sacc[0][3] = fmaf(a0, b3, sacc[0][3]);
            sacc[1][0] = fmaf(a1, b0, sacc[1][0]); sacc[1][1] = fmaf(a1, b1, sacc[1][1]);
            sacc[1][2] = fmaf(a1, b2, sacc[1][2]); sacc[1][3] = fmaf(a1, b3, sacc[1][3]);
            sacc[2][0] = fmaf(a2, b0, sacc[2][0]); sacc[2][1] = fmaf(a2, b1, sacc[2][1]);
            sacc[2][2] = fmaf(a2, b2, sacc[2][2]); sacc[2][3] = fmaf(a2, b3, sacc[2][3]);
            sacc[3][0] = fmaf(a3, b0, sacc[3][0]); sacc[3][1] = fmaf(a3, b1, sacc[3][1]);
            sacc[3][2] = fmaf(a3, b2, sacc[3][2]); sacc[3][3] = fmaf(a3, b3, sacc[3][3]);
        }
        #pragma unroll
        for (int ii = 0; ii < 4; ii++)
            *(float4*)(&Ss[(4 * ty + ii) * APAD + 4 * tx]) =
                make_float4(sacc[ii][0], sacc[ii][1], sacc[ii][2], sacc[ii][3]);
        __syncthreads();

        // online softmax: thread handles row r, cols c0..c0+15
        float sreg[16];
        float mx = -3.0e38f;
        #pragma unroll
        for (int c = 0; c < 16; c++) {
            const int kj  = k0 + c0 + c;
            const int rel = fwd ? (kj - qi) : (qi - kj);
            const float bias = (rel <= 0) ? slope * (float)rel : -1.0e9f;
            const float s = fmaf(Ss[r * APAD + c0 + c], scale, bias);
            sreg[c] = s;
            mx = fmaxf(mx, s);
        }
        mx = fmaxf(mx, __shfl_xor_sync(0xffffffffu, mx, 1));
        mx = fmaxf(mx, __shfl_xor_sync(0xffffffffu, mx, 2));
        const float m_new = fmaxf(m_run, mx);
        const float corr  = __expf(m_run - m_new);
        float lsum = 0.0f;
        #pragma unroll
        for (int c = 0; c < 16; c++) {
            const float p = __expf(sreg[c] - m_new);
            lsum += p;
            Ss[r * APAD + c0 + c] = p;
        }
        lsum += __shfl_xor_sync(0xffffffffu, lsum, 1);
        lsum += __shfl_xor_sync(0xffffffffu, lsum, 2);
        l_run = l_run * corr + lsum;
        m_run = m_new;
        if ((tid & 3) == 0) corr_s[r] = corr;
        __syncthreads();

        // O = O*corr + P V   (thread -> rows 4ty.., dims 4tx..)
        float cf[4];
        #pragma unroll
        for (int ii = 0; ii < 4; ii++) cf[ii] = corr_s[4 * ty + ii];
        #pragma unroll
        for (int ii = 0; ii < 4; ii++)
            #pragma unroll
            for (int dd = 0; dd < 4; dd++)
                o[ii][dd] *= cf[ii];

        #pragma unroll 8
        for (int j = 0; j < 64; j++) {
            float4 vv = *(const float4*)(&Vs[j * APAD + 4 * tx]);
            #pragma unroll
            for (int ii = 0; ii < 4; ii++) {
                const float p = Ss[(4 * ty + ii) * APAD + j];
                o[ii][0] = fmaf(p, vv.x, o[ii][0]);
                o[ii][1] = fmaf(p, vv.y, o[ii][1]);
                o[ii][2] = fmaf(p, vv.z, o[ii][2]);
                o[ii][3] = fmaf(p, vv.w, o[ii][3]);
            }
        }
    }

    if ((tid & 3) == 0) l_s[r] = l_run;
    __syncthreads();

    // write AO in [B,S,H*D]
    const int bi = bh >> 4;
    #pragma unroll
    for (int ii = 0; ii < 4; ii++) {
        const float linv = 1.0f / l_s[4 * ty + ii];
        const int row = q0 + 4 * ty + ii;
        float4 res = make_float4(o[ii][0] * linv, o[ii][1] * linv,
                                 o[ii][2] * linv, o[ii][3] * linv);
        *(float4*)(&AO[((size_t)(bi * S_LEN + row) * MODEL) + h * HD + 4 * tx]) = res;
    }
}

// ---------------------------------------------------------------------------
extern "C" void kernel_launch(void* const* d_in, const int* in_sizes, int n_in,
                              void* d_out, int out_size)
{
    const float* query = (const float*)d_in[0];
    const float* key_i = (const float*)d_in[1];
    const float* value = (const float*)d_in[2];
    const float* Wq = (const float*)d_in[3];
    const float* bq = (const float*)d_in[4];
    const float* Wk = (const float*)d_in[5];
    const float* bk = (const float*)d_in[6];
    const float* Wv = (const float*)d_in[7];
    const float* bv = (const float*)d_in[8];
    const float* Wo = (const float*)d_in[9];
    const float* bo = (const float*)d_in[10];
    float* out = (float*)d_out;

    float* base = nullptr;
    cudaGetSymbolAddress((void**)&base, g_scratch);
    float* qb  = base;
    float* kb  = base + (size_t)QKV_ELEMS;
    float* vb  = base + 2ull * QKV_ELEMS;
    float* aob = base + 3ull * QKV_ELEMS;

    cudaFuncSetAttribute(attn_kernel,
                         cudaFuncAttributeMaxDynamicSharedMemorySize, ATTN_SMEM);

    dim3 gg(MODEL / 128, M_ROWS / 128);   // (8, 64)
    sgemm_bias_kernel<<<gg, 256>>>(query, Wq, bq, qb, MODEL, MODEL, 0);
    sgemm_bias_kernel<<<gg, 256>>>(key_i, Wk, bk, kb, MODEL, MODEL, 0);
    sgemm_bias_kernel<<<gg, 256>>>(value, Wv, bv, vb, MODEL, MODEL, 0);

    dim3 ga(S_LEN / 64, B_SZ * NH);       // (32, 64)
    attn_kernel<<<ga, 256, ATTN_SMEM>>>(qb, kb, vb, aob);

    sgemm_bias_kernel<<<gg, 256>>>(aob, Wo, bo, out, MODEL, MODEL, 1);
}

// round 3
// speedup vs baseline: 1.5091x; 1.5091x over previous
#include <cuda_runtime.h>
#include <cuda_fp16.h>
#include <cstdint>

#define B_SZ   4
#define S_LEN  2048
#define NH     16
#define HD     64
#define MODEL  1024
#define KDIM   1024
#define M_ROWS (B_SZ * S_LEN)                 // 8192
#define QKV_ELEMS (B_SZ * NH * S_LEN * HD)    // 8388608
#define PK     (2 * KDIM)                     // packed halves per row (hi16|lo16 interleave)

// fp32 scratch: q, k, v in [B,H,S,D]
__device__ float g_f32[3ull * QKV_ELEMS];
// packed fp16 hi/lo scratch: Qp, Kp, Vp, AOp (M_ROWS x PK each), then 4 weights (MODEL x PK)
#define HP_QP  0ull
#define HP_KP  (1ull * M_ROWS * PK)
#define HP_VP  (2ull * M_ROWS * PK)
#define HP_AOP (3ull * M_ROWS * PK)
#define HP_W0  (4ull * M_ROWS * PK)
#define HP_WSZ ((unsigned long long)MODEL * PK)
__device__ __half g_h16[4ull * M_ROWS * PK + 4ull * HP_WSZ];

// ============================ helpers ======================================
__device__ __forceinline__ uint32_t smem_u32(const void* p) {
    uint32_t a;
    asm("{ .reg .u64 t; cvta.to.shared.u64 t, %1; cvt.u32.u64 %0, t; }"
        : "=r"(a) : "l"(p));
    return a;
}

__device__ __forceinline__ uint32_t pack2h(float a, float b) {
    __half2 h = __floats2half2_rn(a, b);
    return *reinterpret_cast<uint32_t*>(&h);
}

// split float4 into hi (4 halves) and lo (4 halves), packed as uint2 each
__device__ __forceinline__ void split4(float4 v, uint2& hi, uint2& lo) {
    float hx = __half2float(__float2half_rn(v.x));
    float hy = __half2float(__float2half_rn(v.y));
    float hz = __half2float(__float2half_rn(v.z));
    float hw = __half2float(__float2half_rn(v.w));
    hi.x = pack2h(hx, hy);
    hi.y = pack2h(hz, hw);
    lo.x = pack2h(v.x - hx, v.y - hy);
    lo.y = pack2h(v.z - hz, v.w - hw);
}

#define CP_ASYNC16(dst, src) \
    asm volatile("cp.async.cg.shared.global [%0], [%1], 16;" :: "r"(dst), "l"(src))
#define CP_COMMIT() asm volatile("cp.async.commit_group;")
#define CP_WAIT1()  asm volatile("cp.async.wait_group 1;")
#define CP_WAIT0()  asm volatile("cp.async.wait_group 0;")

#define LDM_X4(r0, r1, r2, r3, addr) \
    asm volatile("ldmatrix.sync.aligned.m8n8.x4.shared.b16 {%0,%1,%2,%3}, [%4];" \
                 : "=r"(r0), "=r"(r1), "=r"(r2), "=r"(r3) : "r"(addr))

#define MMA16816(c, a, b0, b1) \
    asm volatile("mma.sync.aligned.m16n8k16.row.col.f32.f16.f16.f32 " \
                 "{%0,%1,%2,%3}, {%4,%5,%6,%7}, {%8,%9}, {%0,%1,%2,%3};" \
                 : "+f"((c)[0]), "+f"((c)[1]), "+f"((c)[2]), "+f"((c)[3]) \
                 : "r"((a)[0]), "r"((a)[1]), "r"((a)[2]), "r"((a)[3]), \
                   "r"(b0), "r"(b1))

// ============================ split-convert prepass ========================
// src: [rows][1024] fp32 -> dst packed halves [rows][K/16][hi16|lo16]
__global__ __launch_bounds__(256) void cvt_split_kernel(
    const float* __restrict__ src, __half* __restrict__ dst, int n4)
{
    int i = blockIdx.x * blockDim.x + threadIdx.x;
    if (i >= n4) return;
    float4 v = reinterpret_cast<const float4*>(src)[i];
    int row  = i >> 8;               // K/4 = 256 float4 per row
    int kpos = (i & 255) << 2;       // element col
    size_t base = (size_t)row * PK + (size_t)(kpos >> 4) * 32 + (kpos & 15);
    uint2 hi, lo;
    split4(v, hi, lo);
    *reinterpret_cast<uint2*>(dst + base)      = hi;
    *reinterpret_cast<uint2*>(dst + base + 16) = lo;
}

// ============================ fp16-split HMMA GEMM =========================
// C[M,1024] = A @ W^T + bias  (A,W given packed hi/lo fp16).
// CTA tile 128x128, 8 warps (64x32 each), K staged 32 wide, 2-stage cp.async.
// mode 0: scatter into [B,H,S,D]; mode 1: row-major [M,1024].
#define GR 144                      // smem row stride bytes (128 data + 16 pad)
#define STAGE_BYTES (2 * 128 * GR)  // A tile + B tile
#define GEMM_SMEM (2 * STAGE_BYTES) // 73728

__global__ __launch_bounds__(256) void hgemm_split_kernel(
    const __half* __restrict__ Ap, const __half* __restrict__ Wp,
    const float* __restrict__ bias, float* __restrict__ C, int mode)
{
    extern __shared__ char smem[];
    const uint32_t sb = smem_u32(smem);
    const int tid  = threadIdx.x;
    const int lane = tid & 31;
    const int wid  = tid >> 5;
    const int wm   = wid & 1;        // 2 warp-rows x 64
    const int wn   = wid >> 1;       // 4 warp-cols x 32

    const int row0 = blockIdx.y * 128;
    const int col0 = blockIdx.x * 128;

    // cp.async mapping: thread -> (row tid>>1, 64B half (tid&1))
    const int lrow = tid >> 1;
    const int lhalf = (tid & 1) * 4;   // chunk index base (16B chunks)
    const __half* Ag = Ap + (size_t)(row0 + lrow) * PK + lhalf * 8;
    const __half* Wg = Wp + (size_t)(col0 + lrow) * PK + lhalf * 8;
    const uint32_t sA = sb + lrow * GR + lhalf * 16;
    const uint32_t sB = sA + 128 * GR;

    float c[4][4][4];
    #pragma unroll
    for (int mt = 0; mt < 4; mt++)
        #pragma unroll
        for (int nt = 0; nt < 4; nt++)
            #pragma unroll
            for (int q = 0; q < 4; q++)
                c[mt][nt][q] = 0.0f;

    // ldmatrix lane addressing (within warp tile)
    const int arow = wm * 64 + (lane & 7) + ((lane >> 3) & 1) * 8;
    const uint32_t aoff = ((lane >> 4) & 1) * 16;
    const int brow = wn * 32 + (lane & 7) + ((lane >> 4) & 1) * 8;
    const uint32_t boff = ((lane >> 3) & 1) * 16;

    // prologue: stage 0
    #pragma unroll
    for (int i = 0; i < 4; i++) {
        CP_ASYNC16(sA + i * 16, Ag + i * 8);
        CP_ASYNC16(sB + i * 16, Wg + i * 8);
    }
    CP_COMMIT();

    const int NSTAGE = KDIM / 32;     // 32 (each stage = 64 packed halves = 128B)
    for (int s = 0; s < NSTAGE; s++) {
        const int sel = s & 1;
        if (s + 1 < NSTAGE) {
            const int nsel = (s + 1) & 1;
            const __half* Agn = Ag + (size_t)(s + 1) * 64;
            const __half* Wgn = Wg + (size_t)(s + 1) * 64;
            #pragma unroll
            for (int i = 0; i < 4; i++) {
                CP_ASYNC16(sA + nsel * STAGE_BYTES + i * 16, Agn + i * 8);
                CP_ASYNC16(sB + nsel * STAGE_BYTES + i * 16, Wgn + i * 8);
            }
            CP_COMMIT();
            CP_WAIT1();
        } else {
            CP_WAIT0();
        }
        __syncthreads();

        const uint32_t Abase = sb + sel * STAGE_BYTES;
        const uint32_t Bbase = Abase + 128 * GR;

        #pragma unroll
        for (int kk = 0; kk < 2; kk++) {
            uint32_t aH[4][4], aL[4][4], bH[8], bL[8];
            const uint32_t gH = kk * 2, gL = kk * 2 + 1;
            #pragma unroll
            for (int mt = 0; mt < 4; mt++) {
                uint32_t ad = Abase + (arow + mt * 16) * GR + aoff;
                LDM_X4(aH[mt][0], aH[mt][1], aH[mt][2], aH[mt][3], ad + gH * 32);
                LDM_X4(aL[mt][0], aL[mt][1], aL[mt][2], aL[mt][3], ad + gL * 32);
            }
            #pragma unroll
            for (int nt2 = 0; nt2 < 2; nt2++) {
                uint32_t bd = Bbase + (brow + nt2 * 16) * GR + boff;
                LDM_X4(bH[nt2*4+0], bH[nt2*4+1], bH[nt2*4+2], bH[nt2*4+3], bd + gH * 32);
                LDM_X4(bL[nt2*4+0], bL[nt2*4+1], bL[nt2*4+2], bL[nt2*4+3], bd + gL * 32);
            }
            #pragma unroll
            for (int mt = 0; mt < 4; mt++)
                #pragma unroll
                for (int nt = 0; nt < 4; nt++) {
                    MMA16816(c[mt][nt], aH[mt], bH[nt*2], bH[nt*2+1]);
                    MMA16816(c[mt][nt], aH[mt], bL[nt*2], bL[nt*2+1]);
                    MMA16816(c[mt][nt], aL[mt], bH[nt*2], bH[nt*2+1]);
                }
        }
        __syncthreads();
    }

    // epilogue
    const int mrow0 = row0 + wm * 64;
    const int ncol0 = col0 + wn * 32;
    #pragma unroll
    for (int mt = 0; mt < 4; mt++) {
        #pragma unroll
        for (int nt = 0; nt < 4; nt++) {
            const int n = ncol0 + nt * 8 + (lane & 3) * 2;
            const float2 bv = *reinterpret_cast<const float2*>(bias + n);
            const int m1 = mrow0 + mt * 16 + (lane >> 2);
            const int m2 = m1 + 8;
            float2 v1 = make_float2(c[mt][nt][0] + bv.x, c[mt][nt][1] + bv.y);
            float2 v2 = make_float2(c[mt][nt][2] + bv.x, c[mt][nt][3] + bv.y);
            if (mode == 0) {
                const int h = n >> 6, d = n & (HD - 1);
                const int b1 = m1 >> 11, s1 = m1 & (S_LEN - 1);
                const int b2 = m2 >> 11, s2 = m2 & (S_LEN - 1);
                *reinterpret_cast<float2*>(C + (((size_t)(b1 * NH + h) * S_LEN) + s1) * HD + d) = v1;
                *reinterpret_cast<float2*>(C + (((size_t)(b2 * NH + h) * S_LEN) + s2) * HD + d) = v2;
            } else {
                *reinterpret_cast<float2*>(C + (size_t)m1 * MODEL + n) = v1;
                *reinterpret_cast<float2*>(C + (size_t)m2 * MODEL + n) = v2;
            }
        }
    }
}

// ---------------------------------------------------------------------------
// Flash attention with bidirectional ALiBi (fp32), epilogue writes packed
// fp16 hi/lo directly (feeds the final hgemm).
// ---------------------------------------------------------------------------
#define APAD 68
#define ATTN_SMEM ((4 * 64 * APAD + 128) * 4)

__global__ __launch_bounds__(256) void attn_kernel(
    const float* __restrict__ Q, const float* __restrict__ K,
    const float* __restrict__ V, __half* __restrict__ AOp)
{
    extern __shared__ float sm[];
    float* Qs = sm;
    float* Ks = Qs + 64 * APAD;
    float* Vs = Ks + 64 * APAD;
    float* Ss = Vs + 64 * APAD;
    float* corr_s = Ss + 64 * APAD;
    float* l_s    = corr_s + 64;

    const int tid = threadIdx.x;
    const int tx  = tid & 15;
    const int ty  = tid >> 4;
    const int qtile = blockIdx.x;
    const int bh    = blockIdx.y;
    const int h     = bh & (NH - 1);
    const int q0    = qtile * 64;
    const bool fwd  = (h < 8);
    const int sidx  = fwd ? h : (h - 8);
    const float slope = exp2f(-(float)(sidx + 1) * 0.57312031259014454f);
    const float scale = 0.125f;

    const float* Qb = Q + (size_t)bh * S_LEN * HD;
    const float* Kb = K + (size_t)bh * S_LEN * HD;
    const float* Vb = V + (size_t)bh * S_LEN * HD;

    #pragma unroll
    for (int it = 0; it < 4; it++) {
        int idx = tid + it * 256;
        int row = idx >> 4;
        int g4  = (idx & 15) << 2;
        float4 v = *(const float4*)(Qb + (size_t)(q0 + row) * HD + g4);
        Qs[(g4 + 0) * APAD + row] = v.x;
        Qs[(g4 + 1) * APAD + row] = v.y;
        Qs[(g4 + 2) * APAD + row] = v.z;
        Qs[(g4 + 3) * APAD + row] = v.w;
    }

    float o[4][4];
    #pragma unroll
    for (int i = 0; i < 4; i++)
        #pragma unroll
        for (int j = 0; j < 4; j++)
            o[i][j] = 0.0f;

    float m_run = -3.0e38f, l_run = 0.0f;
    const int r  = tid >> 2;
    const int c0 = (tid & 3) * 16;
    const int qi = q0 + r;

    const int kt_begin = fwd ? 0 : qtile;
    const int kt_end   = fwd ? qtile : (S_LEN / 64 - 1);

    for (int kt = kt_begin; kt <= kt_end; kt++) {
        const int k0 = kt * 64;
        __syncthreads();

        #pragma unroll
        for (int it = 0; it < 4; it++) {
            int idx = tid + it * 256;
            int row = idx >> 4;
            int g4  = (idx & 15) << 2;
            float4 kv = *(const float4*)(Kb + (size_t)(k0 + row) * HD + g4);
            Ks[(g4 + 0) * APAD + row] = kv.x;
            Ks[(g4 + 1) * APAD + row] = kv.y;
            Ks[(g4 + 2) * APAD + row] = kv.z;
            Ks[(g4 + 3) * APAD + row] = kv.w;
            float4 vv = *(const float4*)(Vb + (size_t)(k0 + row) * HD + g4);
            *(float4*)(&Vs[row * APAD + g4]) = vv;
        }
        __syncthreads();

        float sacc[4][4];
        #pragma unroll
        for (int i = 0; i < 4; i++)
            #pragma unroll
            for (int j = 0; j < 4; j++)
                sacc[i][j] = 0.0f;

        #pragma unroll 16
        for (int d = 0; d < 64; d++) {
            float4 qa = *(const float4*)(&Qs[d * APAD + 4 * ty]);
            float4 kb = *(const float4*)(&Ks[d * APAD + 4 * tx]);
            float a0 = qa.x, a1 = qa.y, a2 = qa.z, a3 = qa.w;
            float b0 = kb.x, b1 = kb.y, b2 = kb.z, b3 = kb.w;
            sacc[0][0] = fmaf(a0, b0, sacc[0][0]); sacc[0][1] = fmaf(a0, b1, sacc[0][1]);
            sacc[0][2] = fmaf(a0, b2, sacc[0][2]); sacc[0][3] = fmaf(a0, b3, sacc[0][3]);
            sacc[1][0] = fmaf(a1, b0, sacc[1][0]); sacc[1][1] = fmaf(a1, b1, sacc[1][1]);
            sacc[1][2] = fmaf(a1, b2, sacc[1][2]); sacc[1][3] = fmaf(a1, b3, sacc[1][3]);
            sacc[2][0] = fmaf(a2, b0, sacc[2][0]); sacc[2][1] = fmaf(a2, b1, sacc[2][1]);
            sacc[2][2] = fmaf(a2, b2, sacc[2][2]); sacc[2][3] = fmaf(a2, b3, sacc[2][3]);
            sacc[3][0] = fmaf(a3, b0, sacc[3][0]); sacc[3][1] = fmaf(a3, b1, sacc[3][1]);
            sacc[3][2] = fmaf(a3, b2, sacc[3][2]); sacc[3][3] = fmaf(a3, b3, sacc[3][3]);
        }
        #pragma unroll
        for (int ii = 0; ii < 4; ii++)
            *(float4*)(&Ss[(4 * ty + ii) * APAD + 4 * tx]) =
                make_float4(sacc[ii][0], sacc[ii][1], sacc[ii][2], sacc[ii][3]);
        __syncthreads();

        float sreg[16];
        float mx = -3.0e38f;
        #pragma unroll
        for (int cI = 0; cI < 16; cI++) {
            const int kj  = k0 + c0 + cI;
            const int rel = fwd ? (kj - qi) : (qi - kj);
            const float bias = (rel <= 0) ? slope * (float)rel : -1.0e9f;
            const float s = fmaf(Ss[r * APAD + c0 + cI], scale, bias);
            sreg[cI] = s;
            mx = fmaxf(mx, s);
        }
        mx = fmaxf(mx, __shfl_xor_sync(0xffffffffu, mx, 1));
        mx = fmaxf(mx, __shfl_xor_sync(0xffffffffu, mx, 2));
        const float m_new = fmaxf(m_run, mx);
        const float corr  = __expf(m_run - m_new);
        float lsum = 0.0f;
        #pragma unroll
        for (int cI = 0; cI < 16; cI++) {
            const float p = __expf(sreg[cI] - m_new);
            lsum += p;
            Ss[r * APAD + c0 + cI] = p;
        }
        lsum += __shfl_xor_sync(0xffffffffu, lsum, 1);
        lsum += __shfl_xor_sync(0xffffffffu, lsum, 2);
        l_run = l_run * corr + lsum;
        m_run = m_new;
        if ((tid & 3) == 0) corr_s[r] = corr;
        __syncthreads();

        float cf[4];
        #pragma unroll
        for (int ii = 0; ii < 4; ii++) cf[ii] = corr_s[4 * ty + ii];
        #pragma unroll
        for (int ii = 0; ii < 4; ii++)
            #pragma unroll
            for (int dd = 0; dd < 4; dd++)
                o[ii][dd] *= cf[ii];

        #pragma unroll 8
        for (int j = 0; j < 64; j++) {
            float4 vv = *(const float4*)(&Vs[j * APAD + 4 * tx]);
            #pragma unroll
            for (int ii = 0; ii < 4; ii++) {
                const float p = Ss[(4 * ty + ii) * APAD + j];
                o[ii][0] = fmaf(p, vv.x, o[ii][0]);
                o[ii][1] = fmaf(p, vv.y, o[ii][1]);
                o[ii][2] = fmaf(p, vv.z, o[ii][2]);
                o[ii][3] = fmaf(p, vv.w, o[ii][3]);
            }
        }
    }

    if ((tid & 3) == 0) l_s[r] = l_run;
    __syncthreads();

    // epilogue: write packed fp16 hi/lo of attention output [B,S,H*D]
    const int bi = bh >> 4;
    #pragma unroll
    for (int ii = 0; ii < 4; ii++) {
        const float linv = 1.0f / l_s[4 * ty + ii];
        const int row = q0 + 4 * ty + ii;
        float4 res = make_float4(o[ii][0] * linv, o[ii][1] * linv,
                                 o[ii][2] * linv, o[ii][3] * linv);
        const int cc  = h * HD + 4 * tx;                 // model col
        size_t base = (size_t)(bi * S_LEN + row) * PK + (size_t)(cc >> 4) * 32 + (cc & 15);
        uint2 hi, lo;
        split4(res, hi, lo);
        *reinterpret_cast<uint2*>(AOp + base)      = hi;
        *reinterpret_cast<uint2*>(AOp + base + 16) = lo;
    }
}

// ---------------------------------------------------------------------------
extern "C" void kernel_launch(void* const* d_in, const int* in_sizes, int n_in,
                              void* d_out, int out_size)
{
    const float* query = (const float*)d_in[0];
    const float* key_i = (const float*)d_in[1];
    const float* value = (const float*)d_in[2];
    const float* Wq = (const float*)d_in[3];
    const float* bq = (const float*)d_in[4];
    const float* Wk = (const float*)d_in[5];
    const float* bk = (const float*)d_in[6];
    const float* Wv = (const float*)d_in[7];
    const float* bv = (const float*)d_in[8];
    const float* Wo = (const float*)d_in[9];
    const float* bo = (const float*)d_in[10];
    float* out = (float*)d_out;

    float* f32b = nullptr;
    __half* h16b = nullptr;
    cudaGetSymbolAddress((void**)&f32b, g_f32);
    cudaGetSymbolAddress((void**)&h16b, g_h16);

    float* qb = f32b;
    float* kb = f32b + (size_t)QKV_ELEMS;
    float* vb = f32b + 2ull * QKV_ELEMS;
    __half* Qp  = h16b + HP_QP;
    __half* Kp  = h16b + HP_KP;
    __half* Vp  = h16b + HP_VP;
    __half* AOp = h16b + HP_AOP;
    __half* Wqp = h16b + HP_W0;
    __half* Wkp = Wqp + HP_WSZ;
    __half* Wvp = Wkp + HP_WSZ;
    __half* Wop = Wvp + HP_WSZ;

    cudaFuncSetAttribute(hgemm_split_kernel,
                         cudaFuncAttributeMaxDynamicSharedMemorySize, GEMM_SMEM);
    cudaFuncSetAttribute(attn_kernel,
                         cudaFuncAttributeMaxDynamicSharedMemorySize, ATTN_SMEM);

    // split-convert inputs + weights to packed fp16 hi/lo
    const int n4_in = M_ROWS * (KDIM / 4);   // 2,097,152
    const int n4_w  = MODEL * (KDIM / 4);    // 262,144
    cvt_split_kernel<<<n4_in / 256, 256>>>(query, Qp, n4_in);
    cvt_split_kernel<<<n4_in / 256, 256>>>(key_i, Kp, n4_in);
    cvt_split_kernel<<<n4_in / 256, 256>>>(value, Vp, n4_in);
    cvt_split_kernel<<<n4_w / 256, 256>>>(Wq, Wqp, n4_w);
    cvt_split_kernel<<<n4_w / 256, 256>>>(Wk, Wkp, n4_w);
    cvt_split_kernel<<<n4_w / 256, 256>>>(Wv, Wvp, n4_w);
    cvt_split_kernel<<<n4_w / 256, 256>>>(Wo, Wop, n4_w);

    // projections (HMMA fp16-split)
    dim3 gg(MODEL / 128, M_ROWS / 128);      // (8, 64)
    hgemm_split_kernel<<<gg, 256, GEMM_SMEM>>>(Qp, Wqp, bq, qb, 0);
    hgemm_split_kernel<<<gg, 256, GEMM_SMEM>>>(Kp, Wkp, bk, kb, 0);
    hgemm_split_kernel<<<gg, 256, GEMM_SMEM>>>(Vp, Wvp, bv, vb, 0);

    // attention (fp32), writes packed fp16 hi/lo output
    dim3 ga(S_LEN / 64, B_SZ * NH);          // (32, 64)
    attn_kernel<<<ga, 256, ATTN_SMEM>>>(qb, kb, vb, AOp);

    // output projection
    hgemm_split_kernel<<<gg, 256, GEMM_SMEM>>>(AOp, Wop, bo, out, 1);
}

// round 5
// speedup vs baseline: 2.4100x; 1.5970x over previous
#include <cuda_runtime.h>
#include <cuda_fp16.h>
#include <cstdint>

#define B_SZ   4
#define S_LEN  2048
#define NH     16
#define HD     64
#define MODEL  1024
#define KDIM   1024
#define M_ROWS 8192
#define PK     2048      // packed halves per row (hi16|lo16 interleave per 16 elems)
#define NQB    16
#define NKT    32

// ---- packed fp16 scratch layout (halves) ----
#define HP_AQ  0ull
#define HP_AK  (1ull * M_ROWS * PK)
#define HP_AV  (2ull * M_ROWS * PK)
#define HP_AOP (3ull * M_ROWS * PK)
#define HP_WSZ ((unsigned long long)MODEL * PK)
#define HP_W0  (4ull * M_ROWS * PK)
#define BH_SZ  (64ull * S_LEN * 128)
#define HP_QH  (HP_W0 + 4ull * HP_WSZ)
#define HP_KH  (HP_QH + BH_SZ)
#define HP_VH  (HP_KH + BH_SZ)
__device__ __half g_h16[HP_VH + BH_SZ];

// ============================ helpers ======================================
__device__ __forceinline__ uint32_t smem_u32(const void* p) {
    uint32_t a;
    asm("{ .reg .u64 t; cvta.to.shared.u64 t, %1; cvt.u32.u64 %0, t; }"
        : "=r"(a) : "l"(p));
    return a;
}

// split pair of floats into packed hi half2 + lo half2
__device__ __forceinline__ void split2(float x, float y, uint32_t& hi, uint32_t& lo) {
    __half2 h = __floats2half2_rn(x, y);
    float2 f = __half22float2(h);
    __half2 l = __floats2half2_rn(x - f.x, y - f.y);
    hi = *reinterpret_cast<uint32_t*>(&h);
    lo = *reinterpret_cast<uint32_t*>(&l);
}

#define CP_ASYNC16(dst, src) \
    asm volatile("cp.async.cg.shared.global [%0], [%1], 16;" :: "r"(dst), "l"(src))
#define CP_COMMIT() asm volatile("cp.async.commit_group;")
#define CP_WAIT1()  asm volatile("cp.async.wait_group 1;")
#define CP_WAIT0()  asm volatile("cp.async.wait_group 0;")

#define LDM_X4(r0, r1, r2, r3, addr) \
    asm volatile("ldmatrix.sync.aligned.m8n8.x4.shared.b16 {%0,%1,%2,%3}, [%4];" \
                 : "=r"(r0), "=r"(r1), "=r"(r2), "=r"(r3) : "r"(addr))

#define MMA16816(c, a, b0, b1) \
    asm volatile("mma.sync.aligned.m16n8k16.row.col.f32.f16.f16.f32 " \
                 "{%0,%1,%2,%3}, {%4,%5,%6,%7}, {%8,%9}, {%0,%1,%2,%3};" \
                 : "+f"((c)[0]), "+f"((c)[1]), "+f"((c)[2]), "+f"((c)[3]) \
                 : "r"((a)[0]), "r"((a)[1]), "r"((a)[2]), "r"((a)[3]), \
                   "r"(b0), "r"(b1))

// ============================ split-convert prepass ========================
__global__ __launch_bounds__(256) void cvt_split_kernel(
    const float* __restrict__ src, __half* __restrict__ dst, int n4)
{
    int i = blockIdx.x * blockDim.x + threadIdx.x;
    if (i >= n4) return;
    float4 v = reinterpret_cast<const float4*>(src)[i];
    int row  = i >> 8;
    int kpos = (i & 255) << 2;
    size_t base = (size_t)row * PK + (size_t)(kpos >> 4) * 32 + (kpos & 15);
    uint32_t h0, l0, h1, l1;
    split2(v.x, v.y, h0, l0);
    split2(v.z, v.w, h1, l1);
    *reinterpret_cast<uint2*>(dst + base)      = make_uint2(h0, h1);
    *reinterpret_cast<uint2*>(dst + base + 16) = make_uint2(l0, l1);
}

// ============================ fp16-split HMMA GEMM =========================
// C = A @ W^T + bias (A,W packed hi/lo fp16, PK layout).
// mode 0: packed QK attn layout [bh][s][hi64|lo64] (scaled by oscale)
// mode 1: fp32 row-major [M,1024]
// mode 2: packed V transposed [bh][hi-d 0..63, lo-d 64..127][s]
#define GR 144
#define STAGE_BYTES (2 * 128 * GR)
#define GEMM_SMEM (2 * STAGE_BYTES)

__global__ __launch_bounds__(256) void hgemm_split_kernel(
    const __half* __restrict__ Ap, const __half* __restrict__ Wp,
    const float* __restrict__ bias, void* __restrict__ Cv, int mode, float oscale)
{
    extern __shared__ char smem[];
    const uint32_t sb = smem_u32(smem);
    const int tid  = threadIdx.x;
    const int lane = tid & 31;
    const int wid  = tid >> 5;
    const int wm   = wid & 1;
    const int wn   = wid >> 1;

    const int row0 = blockIdx.y * 128;
    const int col0 = blockIdx.x * 128;

    const int lrow = tid >> 1;
    const int lhalf = (tid & 1) * 4;
    const __half* Ag = Ap + (size_t)(row0 + lrow) * PK + lhalf * 8;
    const __half* Wg = Wp + (size_t)(col0 + lrow) * PK + lhalf * 8;
    const uint32_t sA = sb + lrow * GR + lhalf * 16;
    const uint32_t sB = sA + 128 * GR;

    float c[4][4][4];
    #pragma unroll
    for (int mt = 0; mt < 4; mt++)
        #pragma unroll
        for (int nt = 0; nt < 4; nt++)
            #pragma unroll
            for (int q = 0; q < 4; q++)
                c[mt][nt][q] = 0.0f;

    const int arow = wm * 64 + (lane & 7) + ((lane >> 3) & 1) * 8;
    const uint32_t aoff = ((lane >> 4) & 1) * 16;
    const int brow = wn * 32 + (lane & 7) + ((lane >> 4) & 1) * 8;
    const uint32_t boff = ((lane >> 3) & 1) * 16;

    #pragma unroll
    for (int i = 0; i < 4; i++) {
        CP_ASYNC16(sA + i * 16, Ag + i * 8);
        CP_ASYNC16(sB + i * 16, Wg + i * 8);
    }
    CP_COMMIT();

    const int NSTAGE = KDIM / 32;
    for (int s = 0; s < NSTAGE; s++) {
        const int sel = s & 1;
        if (s + 1 < NSTAGE) {
            const int nsel = (s + 1) & 1;
            const __half* Agn = Ag + (size_t)(s + 1) * 64;
            const __half* Wgn = Wg + (size_t)(s + 1) * 64;
            #pragma unroll
            for (int i = 0; i < 4; i++) {
                CP_ASYNC16(sA + nsel * STAGE_BYTES + i * 16, Agn + i * 8);
                CP_ASYNC16(sB + nsel * STAGE_BYTES + i * 16, Wgn + i * 8);
            }
            CP_COMMIT();
            CP_WAIT1();
        } else {
            CP_WAIT0();
        }
        __syncthreads();

        const uint32_t Abase = sb + sel * STAGE_BYTES;
        const uint32_t Bbase = Abase + 128 * GR;

        #pragma unroll
        for (int kk = 0; kk < 2; kk++) {
            uint32_t aH[4][4], aL[4][4], bH[8], bL[8];
            const uint32_t gH = kk * 2, gL = kk * 2 + 1;
            #pragma unroll
            for (int mt = 0; mt < 4; mt++) {
                uint32_t ad = Abase + (arow + mt * 16) * GR + aoff;
                LDM_X4(aH[mt][0], aH[mt][1], aH[mt][2], aH[mt][3], ad + gH * 32);
                LDM_X4(aL[mt][0], aL[mt][1], aL[mt][2], aL[mt][3], ad + gL * 32);
            }
            #pragma unroll
            for (int nt2 = 0; nt2 < 2; nt2++) {
                uint32_t bd = Bbase + (brow + nt2 * 16) * GR + boff;
                LDM_X4(bH[nt2*4+0], bH[nt2*4+1], bH[nt2*4+2], bH[nt2*4+3], bd + gH * 32);
                LDM_X4(bL[nt2*4+0], bL[nt2*4+1], bL[nt2*4+2], bL[nt2*4+3], bd + gL * 32);
            }
            #pragma unroll
            for (int mt = 0; mt < 4; mt++)
                #pragma unroll
                for (int nt = 0; nt < 4; nt++) {
                    MMA16816(c[mt][nt], aH[mt], bH[nt*2], bH[nt*2+1]);
                    MMA16816(c[mt][nt], aH[mt], bL[nt*2], bL[nt*2+1]);
                    MMA16816(c[mt][nt], aL[mt], bH[nt*2], bH[nt*2+1]);
                }
        }
        __syncthreads();
    }

    const int mrow0 = row0 + wm * 64;
    const int ncol0 = col0 + wn * 32;
    #pragma unroll
    for (int mt = 0; mt < 4; mt++) {
        #pragma unroll
        for (int nt = 0; nt < 4; nt++) {
            const int n = ncol0 + nt * 8 + (lane & 3) * 2;
            const float2 bv = *reinterpret_cast<const float2*>(bias + n);
            const int m1 = mrow0 + mt * 16 + (lane >> 2);
            const int m2 = m1 + 8;
            float2 v1 = make_float2((c[mt][nt][0] + bv.x) * oscale,
                                    (c[mt][nt][1] + bv.y) * oscale);
            float2 v2 = make_float2((c[mt][nt][2] + bv.x) * oscale,
                                    (c[mt][nt][3] + bv.y) * oscale);
            if (mode == 1) {
                float* C = (float*)Cv;
                *reinterpret_cast<float2*>(C + (size_t)m1 * MODEL + n) = v1;
                *reinterpret_cast<float2*>(C + (size_t)m2 * MODEL + n) = v2;
            } else {
                __half* H = (__half*)Cv;
                const int hh = n >> 6, d = n & (HD - 1);
                #pragma unroll
                for (int t = 0; t < 2; t++) {
                    const int m = t ? m2 : m1;
                    const float2 v = t ? v2 : v1;
                    const int b = m >> 11, s = m & (S_LEN - 1);
                    const size_t bh = (size_t)(b * NH + hh);
                    uint32_t hi, lo;
                    if (mode == 0) {
                        size_t base = (bh * S_LEN + s) * 128 + d;
                        split2(v.x, v.y, hi, lo);
                        *reinterpret_cast<uint32_t*>(H + base)      = hi;
                        *reinterpret_cast<uint32_t*>(H + base + 64) = lo;
                    } else {  // mode 2: V transposed
                        __half hx = __float2half_rn(v.x);
                        __half hy = __float2half_rn(v.y);
                        __half lx = __float2half_rn(v.x - __half2float(hx));
                        __half ly = __float2half_rn(v.y - __half2float(hy));
                        size_t vb = bh * 128;
                        H[(vb + d)      * S_LEN + s] = hx;
                        H[(vb + d + 1)  * S_LEN + s] = hy;
                        H[(vb + 64 + d) * S_LEN + s] = lx;
                        H[(vb + 65 + d) * S_LEN + s] = ly;
                    }
                }
            }
        }
    }
}

// ======================= HMMA flash attention ==============================
// SINGLE-BUFFERED (R5): load K/V tile -> wait -> sync -> compute -> repeat.
// All softmax arithmetic kept finite: mask/init = -60000 (no 1e9/inf paths).
#define SQ_OFF  0
#define SK_OFF  34816
#define SV_OFF  52224
#define ATTN_SMEM 70656
#define L2E 1.442695040888963f
#define MNEG (-60000.0f)

__global__ __launch_bounds__(256) void attn_h_kernel(
    const __half* __restrict__ Qp, const __half* __restrict__ Kp,
    const __half* __restrict__ Vp, __half* __restrict__ AOp)
{
    extern __shared__ char smc[];
    const uint32_t sb = smem_u32(smc);
    const int tid  = threadIdx.x;
    const int lane = tid & 31;
    const int w    = tid >> 5;
    const int bh   = blockIdx.y;
    const int h    = bh & (NH - 1);
    const bool fwd = (h < 8);
    const int qb   = fwd ? (NQB - 1 - blockIdx.x) : blockIdx.x;
    const int q0   = qb * 128;
    const int sidx = fwd ? h : (h - 8);
    const float slope = exp2f(-(float)(sidx + 1) * 0.57312031259014454f);

    const __half* Qg = Qp + ((size_t)bh * S_LEN + q0) * 128;
    const __half* Kg = Kp + (size_t)bh * S_LEN * 128;
    const __half* Vg = Vp + (size_t)bh * 128 * S_LEN;

    const int kt_begin = fwd ? 0 : 2 * qb;
    const int kt_end   = fwd ? (2 * qb + 1) : (NKT - 1);
    const int ntiles   = kt_end - kt_begin + 1;

    // prologue: Q tile
    #pragma unroll
    for (int i = 0; i < 8; i++) {
        int id = tid + i * 256;
        CP_ASYNC16(sb + SQ_OFF + (id >> 4) * 272 + (id & 15) * 16,
                   Qg + (size_t)(id >> 4) * 128 + (id & 15) * 8);
    }
    CP_COMMIT();
    CP_WAIT0();
    __syncthreads();

    // Q fragments into registers (kept whole kernel)
    uint32_t qh[4][4], ql[4][4];
    {
        const int arow = w * 16 + (lane & 7) + ((lane >> 3) & 1) * 8;
        const uint32_t aoff = ((lane >> 4) & 1) * 16;
        #pragma unroll
        for (int kt = 0; kt < 4; kt++) {
            uint32_t ad = sb + SQ_OFF + arow * 272 + kt * 32 + aoff;
            LDM_X4(qh[kt][0], qh[kt][1], qh[kt][2], qh[kt][3], ad);
            LDM_X4(ql[kt][0], ql[kt][1], ql[kt][2], ql[kt][3], ad + 128);
        }
    }

    float o[8][4];
    #pragma unroll
    for (int nt = 0; nt < 8; nt++)
        #pragma unroll
        for (int q = 0; q < 4; q++)
            o[nt][q] = 0.0f;

    const int g  = lane >> 2;
    const int tq = lane & 3;
    const int row0g = q0 + w * 16 + g;      // rows for c0,c1
    const int row1g = row0g + 8;            // rows for c2,c3
    float m0 = MNEG, m1 = MNEG, l0 = 0.0f, l1 = 0.0f;

    const int brow_base = (lane & 7) + ((lane >> 4) & 1) * 8;
    const uint32_t boff = ((lane >> 3) & 1) * 16;

    for (int it = 0; it < ntiles; it++) {
        const int k0 = (kt_begin + it) * 64;

        __syncthreads();   // prior iteration's smem reads complete
        #pragma unroll
        for (int i = 0; i < 4; i++) {
            int id = tid + i * 256;
            CP_ASYNC16(sb + SK_OFF + (id >> 4) * 272 + (id & 15) * 16,
                       Kg + (size_t)(k0 + (id >> 4)) * 128 + (id & 15) * 8);
        }
        #pragma unroll
        for (int i = 0; i < 4; i++) {
            int id = tid + i * 256;
            CP_ASYNC16(sb + SV_OFF + (id >> 3) * 144 + (id & 7) * 16,
                       Vg + (size_t)(id >> 3) * S_LEN + k0 + (id & 7) * 8);
        }
        CP_COMMIT();
        CP_WAIT0();
        __syncthreads();

        const uint32_t KB = sb + SK_OFF;
        const uint32_t VB = sb + SV_OFF;

        // ---- S = Q K^T (3-pass) ----
        float sc[8][4];
        #pragma unroll
        for (int nt = 0; nt < 8; nt++)
            #pragma unroll
            for (int q = 0; q < 4; q++)
                sc[nt][q] = 0.0f;

        #pragma unroll
        for (int kt = 0; kt < 4; kt++) {
            #pragma unroll
            for (int nt2 = 0; nt2 < 4; nt2++) {
                uint32_t bd = KB + (nt2 * 16 + brow_base) * 272 + kt * 32 + boff;
                uint32_t b0, b1, b2, b3, c0, c1, c2, c3;
                LDM_X4(b0, b1, b2, b3, bd);
                LDM_X4(c0, c1, c2, c3, bd + 128);
                MMA16816(sc[2*nt2],   qh[kt], b0, b1);
                MMA16816(sc[2*nt2],   qh[kt], c0, c1);
                MMA16816(sc[2*nt2],   ql[kt], b0, b1);
                MMA16816(sc[2*nt2+1], qh[kt], b2, b3);
                MMA16816(sc[2*nt2+1], qh[kt], c2, c3);
                MMA16816(sc[2*nt2+1], ql[kt], b2, b3);
            }
        }

        // ---- ALiBi bias + online softmax (registers, all-finite) ----
        float mx0 = MNEG, mx1 = MNEG;
        #pragma unroll
        for (int nt = 0; nt < 8; nt++) {
            const int col = k0 + nt * 8 + tq * 2;
            #pragma unroll
            for (int e = 0; e < 2; e++) {
                const int cj = col + e;
                const int d0 = fwd ? (cj - row0g) : (row0g - cj);
                const int d1 = fwd ? (cj - row1g) : (row1g - cj);
                const float b0f = (d0 > 0) ? MNEG : slope * (float)d0;
                const float b1f = (d1 > 0) ? MNEG : slope * (float)d1;
                sc[nt][e]     += b0f;
                sc[nt][2 + e] += b1f;
                mx0 = fmaxf(mx0, sc[nt][e]);
                mx1 = fmaxf(mx1, sc[nt][2 + e]);
            }
        }
        mx0 = fmaxf(mx0, __shfl_xor_sync(0xffffffffu, mx0, 1));
        mx0 = fmaxf(mx0, __shfl_xor_sync(0xffffffffu, mx0, 2));
        mx1 = fmaxf(mx1, __shfl_xor_sync(0xffffffffu, mx1, 1));
        mx1 = fmaxf(mx1, __shfl_xor_sync(0xffffffffu, mx1, 2));
        const float mn0 = fmaxf(m0, mx0);
        const float mn1 = fmaxf(m1, mx1);
        const float corr0 = exp2f((m0 - mn0) * L2E);
        const float corr1 = exp2f((m1 - mn1) * L2E);
        const float s0 = mn0 * L2E, s1 = mn1 * L2E;
        float ls0 = 0.0f, ls1 = 0.0f;
        #pragma unroll
        for (int nt = 0; nt < 8; nt++) {
            float p0 = exp2f(fmaf(sc[nt][0], L2E, -s0));
            float p1 = exp2f(fmaf(sc[nt][1], L2E, -s0));
            float p2 = exp2f(fmaf(sc[nt][2], L2E, -s1));
            float p3 = exp2f(fmaf(sc[nt][3], L2E, -s1));
            sc[nt][0] = p0; sc[nt][1] = p1; sc[nt][2] = p2; sc[nt][3] = p3;
            ls0 += p0 + p1;
            ls1 += p2 + p3;
        }
        ls0 += __shfl_xor_sync(0xffffffffu, ls0, 1);
        ls0 += __shfl_xor_sync(0xffffffffu, ls0, 2);
        ls1 += __shfl_xor_sync(0xffffffffu, ls1, 1);
        ls1 += __shfl_xor_sync(0xffffffffu, ls1, 2);
        l0 = l0 * corr0 + ls0;
        l1 = l1 * corr1 + ls1;
        m0 = mn0;
        m1 = mn1;
        #pragma unroll
        for (int nt = 0; nt < 8; nt++) {
            o[nt][0] *= corr0; o[nt][1] *= corr0;
            o[nt][2] *= corr1; o[nt][3] *= corr1;
        }

        // ---- O += P V (3-pass; P repacked from S fragments) ----
        #pragma unroll
        for (int kt = 0; kt < 4; kt++) {
            uint32_t ah[4], al[4];
            split2(sc[2*kt][0],   sc[2*kt][1],   ah[0], al[0]);
            split2(sc[2*kt][2],   sc[2*kt][3],   ah[1], al[1]);
            split2(sc[2*kt+1][0], sc[2*kt+1][1], ah[2], al[2]);
            split2(sc[2*kt+1][2], sc[2*kt+1][3], ah[3], al[3]);
            #pragma unroll
            for (int nt2 = 0; nt2 < 4; nt2++) {
                uint32_t vd = VB + (nt2 * 16 + brow_base) * 144 + kt * 32 + boff;
                uint32_t b0, b1, b2, b3, c0, c1, c2, c3;
                LDM_X4(b0, b1, b2, b3, vd);
                LDM_X4(c0, c1, c2, c3, vd + 64 * 144);
                MMA16816(o[2*nt2],   ah, b0, b1);
                MMA16816(o[2*nt2],   ah, c0, c1);
                MMA16816(o[2*nt2],   al, b0, b1);
                MMA16816(o[2*nt2+1], ah, b2, b3);
                MMA16816(o[2*nt2+1], ah, c2, c3);
                MMA16816(o[2*nt2+1], al, b2, b3);
            }
        }
    }

    // ---- epilogue: O /= l, write packed hi/lo into AOp (PK layout) ----
    const float inv0 = 1.0f / l0;
    const float inv1 = 1.0f / l1;
    const int bi = bh >> 4;
    const size_t ar0 = (size_t)(bi * S_LEN) + row0g;
    #pragma unroll
    for (int nt = 0; nt < 8; nt++) {
        const int cc = h * HD + nt * 8 + tq * 2;
        const size_t coff = (size_t)(cc >> 4) * 32 + (cc & 15);
        uint32_t hi, lo;
        split2(o[nt][0] * inv0, o[nt][1] * inv0, hi, lo);
        *reinterpret_cast<uint32_t*>(AOp + ar0 * PK + coff)      = hi;
        *reinterpret_cast<uint32_t*>(AOp + ar0 * PK + coff + 16) = lo;
        split2(o[nt][2] * inv1, o[nt][3] * inv1, hi, lo);
        *reinterpret_cast<uint32_t*>(AOp + (ar0 + 8) * PK + coff)      = hi;
        *reinterpret_cast<uint32_t*>(AOp + (ar0 + 8) * PK + coff + 16) = lo;
    }
}

// ---------------------------------------------------------------------------
extern "C" void kernel_launch(void* const* d_in, const int* in_sizes, int n_in,
                              void* d_out, int out_size)
{
    const float* query = (const float*)d_in[0];
    const float* key_i = (const float*)d_in[1];
    const float* value = (const float*)d_in[2];
    const float* Wq = (const float*)d_in[3];
    const float* bq = (const float*)d_in[4];
    const float* Wk = (const float*)d_in[5];
    const float* bk = (const float*)d_in[6];
    const float* Wv = (const float*)d_in[7];
    const float* bv = (const float*)d_in[8];
    const float* Wo = (const float*)d_in[9];
    const float* bo = (const float*)d_in[10];
    float* out = (float*)d_out;

    __half* hb = nullptr;
    cudaGetSymbolAddress((void**)&hb, g_h16);
    __half* AQ  = hb + HP_AQ;
    __half* AK  = hb + HP_AK;
    __half* AV  = hb + HP_AV;
    __half* AOp = hb + HP_AOP;
    __half* Wqp = hb + HP_W0;
    __half* Wkp = Wqp + HP_WSZ;
    __half* Wvp = Wkp + HP_WSZ;
    __half* Wop = Wvp + HP_WSZ;
    __half* QH  = hb + HP_QH;
    __half* KH  = hb + HP_KH;
    __half* VH  = hb + HP_VH;

    cudaFuncSetAttribute(hgemm_split_kernel,
                         cudaFuncAttributeMaxDynamicSharedMemorySize, GEMM_SMEM);
    cudaFuncSetAttribute(attn_h_kernel,
                         cudaFuncAttributeMaxDynamicSharedMemorySize, ATTN_SMEM);

    const int n4_in = M_ROWS * (KDIM / 4);
    const int n4_w  = MODEL * (KDIM / 4);
    cvt_split_kernel<<<n4_in / 256, 256>>>(query, AQ, n4_in);
    cvt_split_kernel<<<n4_in / 256, 256>>>(key_i, AK, n4_in);
    cvt_split_kernel<<<n4_in / 256, 256>>>(value, AV, n4_in);
    cvt_split_kernel<<<n4_w / 256, 256>>>(Wq, Wqp, n4_w);
    cvt_split_kernel<<<n4_w / 256, 256>>>(Wk, Wkp, n4_w);
    cvt_split_kernel<<<n4_w / 256, 256>>>(Wv, Wvp, n4_w);
    cvt_split_kernel<<<n4_w / 256, 256>>>(Wo, Wop, n4_w);

    dim3 gg(MODEL / 128, M_ROWS / 128);      // (8, 64)
    hgemm_split_kernel<<<gg, 256, GEMM_SMEM>>>(AQ, Wqp, bq, QH, 0, 0.125f);
    hgemm_split_kernel<<<gg, 256, GEMM_SMEM>>>(AK, Wkp, bk, KH, 0, 1.0f);
    hgemm_split_kernel<<<gg, 256, GEMM_SMEM>>>(AV, Wvp, bv, VH, 2, 1.0f);

    dim3 ga(NQB, B_SZ * NH);                 // (16, 64)
    attn_h_kernel<<<ga, 256, ATTN_SMEM>>>(QH, KH, VH, AOp);

    hgemm_split_kernel<<<gg, 256, GEMM_SMEM>>>(AOp, Wop, bo, out, 1, 1.0f);
}

// round 7
// speedup vs baseline: 2.4606x; 1.0210x over previous
#include <cuda_runtime.h>
#include <cuda_fp16.h>
#include <cstdint>

#define B_SZ   4
#define S_LEN  2048
#define NH     16
#define HD     64
#define MODEL  1024
#define KDIM   1024
#define M_ROWS 8192
#define PK     2048      // packed halves per row (hi16|lo16 interleave per 16 elems)
#define NQB    16
#define NKT    32

// ---- packed fp16 scratch layout (halves) ----
#define HP_AQ  0ull
#define HP_AK  (1ull * M_ROWS * PK)
#define HP_AV  (2ull * M_ROWS * PK)
#define HP_AOP (3ull * M_ROWS * PK)
#define HP_WSZ ((unsigned long long)MODEL * PK)
#define HP_W0  (4ull * M_ROWS * PK)
#define BH_SZ  (64ull * S_LEN * 128)
#define HP_QH  (HP_W0 + 4ull * HP_WSZ)
#define HP_KH  (HP_QH + BH_SZ)
#define HP_VH  (HP_KH + BH_SZ)
__device__ __half g_h16[HP_VH + BH_SZ];

// ============================ helpers ======================================
__device__ __forceinline__ uint32_t smem_u32(const void* p) {
    uint32_t a;
    asm("{ .reg .u64 t; cvta.to.shared.u64 t, %1; cvt.u32.u64 %0, t; }"
        : "=r"(a) : "l"(p));
    return a;
}

// split pair of floats into packed hi half2 + lo half2
__device__ __forceinline__ void split2(float x, float y, uint32_t& hi, uint32_t& lo) {
    __half2 h = __floats2half2_rn(x, y);
    float2 f = __half22float2(h);
    __half2 l = __floats2half2_rn(x - f.x, y - f.y);
    hi = *reinterpret_cast<uint32_t*>(&h);
    lo = *reinterpret_cast<uint32_t*>(&l);
}

#define CP_ASYNC16(dst, src) \
    asm volatile("cp.async.cg.shared.global [%0], [%1], 16;" :: "r"(dst), "l"(src))
#define CP_COMMIT() asm volatile("cp.async.commit_group;")
#define CP_WAIT1()  asm volatile("cp.async.wait_group 1;")
#define CP_WAIT0()  asm volatile("cp.async.wait_group 0;")

#define LDM_X4(r0, r1, r2, r3, addr) \
    asm volatile("ldmatrix.sync.aligned.m8n8.x4.shared.b16 {%0,%1,%2,%3}, [%4];" \
                 : "=r"(r0), "=r"(r1), "=r"(r2), "=r"(r3) : "r"(addr))

#define MMA16816(c, a, b0, b1) \
    asm volatile("mma.sync.aligned.m16n8k16.row.col.f32.f16.f16.f32 " \
                 "{%0,%1,%2,%3}, {%4,%5,%6,%7}, {%8,%9}, {%0,%1,%2,%3};" \
                 : "+f"((c)[0]), "+f"((c)[1]), "+f"((c)[2]), "+f"((c)[3]) \
                 : "r"((a)[0]), "r"((a)[1]), "r"((a)[2]), "r"((a)[3]), \
                   "r"(b0), "r"(b1))

// ============================ split-convert prepass ========================
__global__ __launch_bounds__(256) void cvt_split_kernel(
    const float* __restrict__ src, __half* __restrict__ dst, int n4)
{
    int i = blockIdx.x * blockDim.x + threadIdx.x;
    if (i >= n4) return;
    float4 v = reinterpret_cast<const float4*>(src)[i];
    int row  = i >> 8;
    int kpos = (i & 255) << 2;
    size_t base = (size_t)row * PK + (size_t)(kpos >> 4) * 32 + (kpos & 15);
    uint32_t h0, l0, h1, l1;
    split2(v.x, v.y, h0, l0);
    split2(v.z, v.w, h1, l1);
    *reinterpret_cast<uint2*>(dst + base)      = make_uint2(h0, h1);
    *reinterpret_cast<uint2*>(dst + base + 16) = make_uint2(l0, l1);
}

// ============================ fp16-split HMMA GEMM =========================
// C = A @ W^T + bias.  CTA tile 128x256, 8 warps in 2x4 grid, 64x64 warp tile.
// K staged 32 wide, 2-stage cp.async pipeline.
// mode 0: packed QK attn layout [bh][s][hi64|lo64] (scaled by oscale)
// mode 1: fp32 row-major [M,1024]
// mode 2: packed V transposed [bh][hi-d 0..63, lo-d 64..127][s]
#define GR 144
#define A_BYTES (128 * GR)                 // 18432
#define B_BYTES (256 * GR)                 // 36864
#define STAGE_BYTES (A_BYTES + B_BYTES)    // 55296
#define GEMM_SMEM (2 * STAGE_BYTES)        // 110592

__global__ __launch_bounds__(256) void hgemm_split_kernel(
    const __half* __restrict__ Ap, const __half* __restrict__ Wp,
    const float* __restrict__ bias, void* __restrict__ Cv, int mode, float oscale)
{
    extern __shared__ char smem[];
    const uint32_t sb = smem_u32(smem);
    const int tid  = threadIdx.x;
    const int lane = tid & 31;
    const int wid  = tid >> 5;
    const int wm   = wid >> 2;       // 2 warp-rows x 64
    const int wn   = wid & 3;        // 4 warp-cols x 64

    const int row0 = blockIdx.y * 128;
    const int col0 = blockIdx.x * 256;

    // load mapping: 2 threads per row, 4x16B chunks each
    const int lrow  = tid >> 1;
    const int lhalf = (tid & 1) * 4;
    const __half* Ag  = Ap + (size_t)(row0 + lrow) * PK + lhalf * 8;
    const __half* Wg0 = Wp + (size_t)(col0 + lrow) * PK + lhalf * 8;
    const __half* Wg1 = Wp + (size_t)(col0 + 128 + lrow) * PK + lhalf * 8;
    const uint32_t sA  = sb + lrow * GR + lhalf * 16;
    const uint32_t sB0 = sb + A_BYTES + lrow * GR + lhalf * 16;
    const uint32_t sB1 = sB0 + 128 * GR;

    float c[4][8][4];
    #pragma unroll
    for (int mt = 0; mt < 4; mt++)
        #pragma unroll
        for (int nt = 0; nt < 8; nt++)
            #pragma unroll
            for (int q = 0; q < 4; q++)
                c[mt][nt][q] = 0.0f;

    const int arow = wm * 64 + (lane & 7) + ((lane >> 3) & 1) * 8;
    const uint32_t aoff = ((lane >> 4) & 1) * 16;
    const int brow_base = (lane & 7) + ((lane >> 4) & 1) * 8;
    const uint32_t boff = ((lane >> 3) & 1) * 16;

    // prologue: stage 0
    #pragma unroll
    for (int i = 0; i < 4; i++) {
        CP_ASYNC16(sA  + i * 16, Ag  + i * 8);
        CP_ASYNC16(sB0 + i * 16, Wg0 + i * 8);
        CP_ASYNC16(sB1 + i * 16, Wg1 + i * 8);
    }
    CP_COMMIT();

    const int NSTAGE = KDIM / 32;     // 32
    for (int s = 0; s < NSTAGE; s++) {
        const int sel = s & 1;
        if (s + 1 < NSTAGE) {
            const uint32_t st = ((s + 1) & 1) * STAGE_BYTES;
            const size_t so = (size_t)(s + 1) * 64;
            #pragma unroll
            for (int i = 0; i < 4; i++) {
                CP_ASYNC16(sA  + st + i * 16, Ag  + so + i * 8);
                CP_ASYNC16(sB0 + st + i * 16, Wg0 + so + i * 8);
                CP_ASYNC16(sB1 + st + i * 16, Wg1 + so + i * 8);
            }
            CP_COMMIT();
            CP_WAIT1();
        } else {
            CP_WAIT0();
        }
        __syncthreads();

        const uint32_t Abase = sb + sel * STAGE_BYTES;
        const uint32_t Bbase = Abase + A_BYTES;

        #pragma unroll
        for (int kk = 0; kk < 2; kk++) {
            uint32_t aH[4][4], aL[4][4];
            #pragma unroll
            for (int mt = 0; mt < 4; mt++) {
                uint32_t ad = Abase + (arow + mt * 16) * GR + kk * 64 + aoff;
                LDM_X4(aH[mt][0], aH[mt][1], aH[mt][2], aH[mt][3], ad);
                LDM_X4(aL[mt][0], aL[mt][1], aL[mt][2], aL[mt][3], ad + 32);
            }
            #pragma unroll
            for (int nt2 = 0; nt2 < 4; nt2++) {
                uint32_t bd = Bbase + (wn * 64 + nt2 * 16 + brow_base) * GR + kk * 64 + boff;
                uint32_t bH0, bH1, bH2, bH3, bL0, bL1, bL2, bL3;
                LDM_X4(bH0, bH1, bH2, bH3, bd);
                LDM_X4(bL0, bL1, bL2, bL3, bd + 32);
                #pragma unroll
                for (int mt = 0; mt < 4; mt++) {
                    MMA16816(c[mt][2*nt2],   aH[mt], bH0, bH1);
                    MMA16816(c[mt][2*nt2],   aH[mt], bL0, bL1);
                    MMA16816(c[mt][2*nt2],   aL[mt], bH0, bH1);
                    MMA16816(c[mt][2*nt2+1], aH[mt], bH2, bH3);
                    MMA16816(c[mt][2*nt2+1], aH[mt], bL2, bL3);
                    MMA16816(c[mt][2*nt2+1], aL[mt], bH2, bH3);
                }
            }
        }
        __syncthreads();
    }

    const int mrow0 = row0 + wm * 64;
    const int ncol0 = col0 + wn * 64;
    #pragma unroll
    for (int mt = 0; mt < 4; mt++) {
        #pragma unroll
        for (int nt = 0; nt < 8; nt++) {
            const int n = ncol0 + nt * 8 + (lane & 3) * 2;
            const float2 bv = *reinterpret_cast<const float2*>(bias + n);
            const int m1 = mrow0 + mt * 16 + (lane >> 2);
            const int m2 = m1 + 8;
            float2 v1 = make_float2((c[mt][nt][0] + bv.x) * oscale,
                                    (c[mt][nt][1] + bv.y) * oscale);
            float2 v2 = make_float2((c[mt][nt][2] + bv.x) * oscale,
                                    (c[mt][nt][3] + bv.y) * oscale);
            if (mode == 1) {
                float* C = (float*)Cv;
                *reinterpret_cast<float2*>(C + (size_t)m1 * MODEL + n) = v1;
                *reinterpret_cast<float2*>(C + (size_t)m2 * MODEL + n) = v2;
            } else {
                __half* H = (__half*)Cv;
                const int hh = n >> 6, d = n & (HD - 1);
                #pragma unroll
                for (int t = 0; t < 2; t++) {
                    const int m = t ? m2 : m1;
                    const float2 v = t ? v2 : v1;
                    const int b = m >> 11, s = m & (S_LEN - 1);
                    const size_t bh = (size_t)(b * NH + hh);
                    uint32_t hi, lo;
                    if (mode == 0) {
                        size_t base = (bh * S_LEN + s) * 128 + d;
                        split2(v.x, v.y, hi, lo);
                        *reinterpret_cast<uint32_t*>(H + base)      = hi;
                        *reinterpret_cast<uint32_t*>(H + base + 64) = lo;
                    } else {  // mode 2: V transposed
                        __half hx = __float2half_rn(v.x);
                        __half hy = __float2half_rn(v.y);
                        __half lx = __float2half_rn(v.x - __half2float(hx));
                        __half ly = __float2half_rn(v.y - __half2float(hy));
                        size_t vb = bh * 128;
                        H[(vb + d)      * S_LEN + s] = hx;
                        H[(vb + d + 1)  * S_LEN + s] = hy;
                        H[(vb + 64 + d) * S_LEN + s] = lx;
                        H[(vb + 65 + d) * S_LEN + s] = ly;
                    }
                }
            }
        }
    }
}

// ======================= HMMA flash attention ==============================
// DOUBLE-BUFFERED K/V (R6); all-finite softmax (mask/init = -60000).
#define SQ_OFF  0
#define SK0_OFF 34816
#define SK1_OFF 52224
#define SV0_OFF 69632
#define SV1_OFF 88064
#define ATTN_SMEM 106496
#define L2E 1.442695040888963f
#define MNEG (-60000.0f)

__global__ __launch_bounds__(256) void attn_h_kernel(
    const __half* __restrict__ Qp, const __half* __restrict__ Kp,
    const __half* __restrict__ Vp, __half* __restrict__ AOp)
{
    extern __shared__ char smc[];
    const uint32_t sb = smem_u32(smc);
    const int tid  = threadIdx.x;
    const int lane = tid & 31;
    const int w    = tid >> 5;
    const int bh   = blockIdx.y;
    const int h    = bh & (NH - 1);
    const bool fwd = (h < 8);
    const int qb   = fwd ? (NQB - 1 - blockIdx.x) : blockIdx.x;
    const int q0   = qb * 128;
    const int sidx = fwd ? h : (h - 8);
    const float slope = exp2f(-(float)(sidx + 1) * 0.57312031259014454f);

    const __half* Qg = Qp + ((size_t)bh * S_LEN + q0) * 128;
    const __half* Kg = Kp + (size_t)bh * S_LEN * 128;
    const __half* Vg = Vp + (size_t)bh * 128 * S_LEN;

    const int kt_begin = fwd ? 0 : 2 * qb;
    const int kt_end   = fwd ? (2 * qb + 1) : (NKT - 1);
    const int ntiles   = kt_end - kt_begin + 1;

    // prologue: Q tile + first K/V tile (one group)
    #pragma unroll
    for (int i = 0; i < 8; i++) {
        int id = tid + i * 256;
        CP_ASYNC16(sb + SQ_OFF + (id >> 4) * 272 + (id & 15) * 16,
                   Qg + (size_t)(id >> 4) * 128 + (id & 15) * 8);
    }
    {
        const int k0 = kt_begin * 64;
        #pragma unroll
        for (int i = 0; i < 4; i++) {
            int id = tid + i * 256;
            CP_ASYNC16(sb + SK0_OFF + (id >> 4) * 272 + (id & 15) * 16,
                       Kg + (size_t)(k0 + (id >> 4)) * 128 + (id & 15) * 8);
        }
        #pragma unroll
        for (int i = 0; i < 4; i++) {
            int id = tid + i * 256;
            CP_ASYNC16(sb + SV0_OFF + (id >> 3) * 144 + (id & 7) * 16,
                       Vg + (size_t)(id >> 3) * S_LEN + k0 + (id & 7) * 8);
        }
    }
    CP_COMMIT();
    CP_WAIT0();
    __syncthreads();

    // Q fragments into registers (kept whole kernel)
    uint32_t qh[4][4], ql[4][4];
    {
        const int arow = w * 16 + (lane & 7) + ((lane >> 3) & 1) * 8;
        const uint32_t aoff = ((lane >> 4) & 1) * 16;
        #pragma unroll
        for (int kt = 0; kt < 4; kt++) {
            uint32_t ad = sb + SQ_OFF + arow * 272 + kt * 32 + aoff;
            LDM_X4(qh[kt][0], qh[kt][1], qh[kt][2], qh[kt][3], ad);
            LDM_X4(ql[kt][0], ql[kt][1], ql[kt][2], ql[kt][3], ad + 128);
        }
    }

    float o[8][4];
    #pragma unroll
    for (int nt = 0; nt < 8; nt++)
        #pragma unroll
        for (int q = 0; q < 4; q++)
            o[nt][q] = 0.0f;

    const int g  = lane >> 2;
    const int tq = lane & 3;
    const int row0g = q0 + w * 16 + g;
    const int row1g = row0g + 8;
    float m0 = MNEG, m1 = MNEG, l0 = 0.0f, l1 = 0.0f;

    const int brow_base = (lane & 7) + ((lane >> 4) & 1) * 8;
    const uint32_t boff = ((lane >> 3) & 1) * 16;

    for (int it = 0; it < ntiles; it++) {
        const int k0 = (kt_begin + it) * 64;
        const int sel = it & 1;
        if (it + 1 < ntiles) {
            const int nk0 = (kt_begin + it + 1) * 64;
            const uint32_t dk = sb + ((it + 1) & 1 ? SK1_OFF : SK0_OFF);
            const uint32_t dv = sb + ((it + 1) & 1 ? SV1_OFF : SV0_OFF);
            #pragma unroll
            for (int i = 0; i < 4; i++) {
                int id = tid + i * 256;
                CP_ASYNC16(dk + (id >> 4) * 272 + (id & 15) * 16,
                           Kg + (size_t)(nk0 + (id >> 4)) * 128 + (id & 15) * 8);
            }
            #pragma unroll
            for (int i = 0; i < 4; i++) {
                int id = tid + i * 256;
                CP_ASYNC16(dv + (id >> 3) * 144 + (id & 7) * 16,
                           Vg + (size_t)(id >> 3) * S_LEN + nk0 + (id & 7) * 8);
            }
            CP_COMMIT();
            CP_WAIT1();
        } else {
            CP_WAIT0();
        }
        __syncthreads();

        const uint32_t KB = sb + (sel ? SK1_OFF : SK0_OFF);
        const uint32_t VB = sb + (sel ? SV1_OFF : SV0_OFF);

        // ---- S = Q K^T (3-pass) ----
        float sc[8][4];
        #pragma unroll
        for (int nt = 0; nt < 8; nt++)
            #pragma unroll
            for (int q = 0; q < 4; q++)
                sc[nt][q] = 0.0f;

        #pragma unroll
        for (int kt = 0; kt < 4; kt++) {
            #pragma unroll
            for (int nt2 = 0; nt2 < 4; nt2++) {
                uint32_t bd = KB + (nt2 * 16 + brow_base) * 272 + kt * 32 + boff;
                uint32_t b0, b1, b2, b3, c0, c1, c2, c3;
                LDM_X4(b0, b1, b2, b3, bd);
                LDM_X4(c0, c1, c2, c3, bd + 128);
                MMA16816(sc[2*nt2],   qh[kt], b0, b1);
                MMA16816(sc[2*nt2],   qh[kt], c0, c1);
                MMA16816(sc[2*nt2],   ql[kt], b0, b1);
                MMA16816(sc[2*nt2+1], qh[kt], b2, b3);
                MMA16816(sc[2*nt2+1], qh[kt], c2, c3);
                MMA16816(sc[2*nt2+1], ql[kt], b2, b3);
            }
        }

        // ---- ALiBi bias + online softmax (registers, all-finite) ----
        float mx0 = MNEG, mx1 = MNEG;
        #pragma unroll
        for (int nt = 0; nt < 8; nt++) {
            const int col = k0 + nt * 8 + tq * 2;
            #pragma unroll
            for (int e = 0; e < 2; e++) {
                const int cj = col + e;
                const int d0 = fwd ? (cj - row0g) : (row0g - cj);
                const int d1 = fwd ? (cj - row1g) : (row1g - cj);
                const float b0f = (d0 > 0) ? MNEG : slope * (float)d0;
                const float b1f = (d1 > 0) ? MNEG : slope * (float)d1;
                sc[nt][e]     += b0f;
                sc[nt][2 + e] += b1f;
                mx0 = fmaxf(mx0, sc[nt][e]);
                mx1 = fmaxf(mx1, sc[nt][2 + e]);
            }
        }
        mx0 = fmaxf(mx0, __shfl_xor_sync(0xffffffffu, mx0, 1));
        mx0 = fmaxf(mx0, __shfl_xor_sync(0xffffffffu, mx0, 2));
        mx1 = fmaxf(mx1, __shfl_xor_sync(0xffffffffu, mx1, 1));
        mx1 = fmaxf(mx1, __shfl_xor_sync(0xffffffffu, mx1, 2));
        const float mn0 = fmaxf(m0, mx0);
        const float mn1 = fmaxf(m1, mx1);
        const float corr0 = exp2f((m0 - mn0) * L2E);
        const float corr1 = exp2f((m1 - mn1) * L2E);
        const float s0 = mn0 * L2E, s1 = mn1 * L2E;
        float ls0 = 0.0f, ls1 = 0.0f;
        #pragma unroll
        for (int nt = 0; nt < 8; nt++) {
            float p0 = exp2f(fmaf(sc[nt][0], L2E, -s0));
            float p1 = exp2f(fmaf(sc[nt][1], L2E, -s0));
            float p2 = exp2f(fmaf(sc[nt][2], L2E, -s1));
            float p3 = exp2f(fmaf(sc[nt][3], L2E, -s1));
            sc[nt][0] = p0; sc[nt][1] = p1; sc[nt][2] = p2; sc[nt][3] = p3;
            ls0 += p0 + p1;
            ls1 += p2 + p3;
        }
        ls0 += __shfl_xor_sync(0xffffffffu, ls0, 1);
        ls0 += __shfl_xor_sync(0xffffffffu, ls0, 2);
        ls1 += __shfl_xor_sync(0xffffffffu, ls1, 1);
        ls1 += __shfl_xor_sync(0xffffffffu, ls1, 2);
        l0 = l0 * corr0 + ls0;
        l1 = l1 * corr1 + ls1;
        m0 = mn0;
        m1 = mn1;
        #pragma unroll
        for (int nt = 0; nt < 8; nt++) {
            o[nt][0] *= corr0; o[nt][1] *= corr0;
            o[nt][2] *= corr1; o[nt][3] *= corr1;
        }

        // ---- O += P V (3-pass; P repacked from S fragments) ----
        #pragma unroll
        for (int kt = 0; kt < 4; kt++) {
            uint32_t ah[4], al[4];
            split2(sc[2*kt][0],   sc[2*kt][1],   ah[0], al[0]);
            split2(sc[2*kt][2],   sc[2*kt][3],   ah[1], al[1]);
            split2(sc[2*kt+1][0], sc[2*kt+1][1], ah[2], al[2]);
            split2(sc[2*kt+1][2], sc[2*kt+1][3], ah[3], al[3]);
            #pragma unroll
            for (int nt2 = 0; nt2 < 4; nt2++) {
                uint32_t vd = VB + (nt2 * 16 + brow_base) * 144 + kt * 32 + boff;
                uint32_t b0, b1, b2, b3, c0, c1, c2, c3;
                LDM_X4(b0, b1, b2, b3, vd);
                LDM_X4(c0, c1, c2, c3, vd + 64 * 144);
                MMA16816(o[2*nt2],   ah, b0, b1);
                MMA16816(o[2*nt2],   ah, c0, c1);
                MMA16816(o[2*nt2],   al, b0, b1);
                MMA16816(o[2*nt2+1], ah, b2, b3);
                MMA16816(o[2*nt2+1], ah, c2, c3);
                MMA16816(o[2*nt2+1], al, b2, b3);
            }
        }
        __syncthreads();
    }

    // ---- epilogue: O /= l, write packed hi/lo into AOp (PK layout) ----
    const float inv0 = 1.0f / l0;
    const float inv1 = 1.0f / l1;
    const int bi = bh >> 4;
    const size_t ar0 = (size_t)(bi * S_LEN) + row0g;
    #pragma unroll
    for (int nt = 0; nt < 8; nt++) {
        const int cc = h * HD + nt * 8 + tq * 2;
        const size_t coff = (size_t)(cc >> 4) * 32 + (cc & 15);
        uint32_t hi, lo;
        split2(o[nt][0] * inv0, o[nt][1] * inv0, hi, lo);
        *reinterpret_cast<uint32_t*>(AOp + ar0 * PK + coff)      = hi;
        *reinterpret_cast<uint32_t*>(AOp + ar0 * PK + coff + 16) = lo;
        split2(o[nt][2] * inv1, o[nt][3] * inv1, hi, lo);
        *reinterpret_cast<uint32_t*>(AOp + (ar0 + 8) * PK + coff)      = hi;
        *reinterpret_cast<uint32_t*>(AOp + (ar0 + 8) * PK + coff + 16) = lo;
    }
}

// ---------------------------------------------------------------------------
extern "C" void kernel_launch(void* const* d_in, const int* in_sizes, int n_in,
                              void* d_out, int out_size)
{
    const float* query = (const float*)d_in[0];
    const float* key_i = (const float*)d_in[1];
    const float* value = (const float*)d_in[2];
    const float* Wq = (const float*)d_in[3];
    const float* bq = (const float*)d_in[4];
    const float* Wk = (const float*)d_in[5];
    const float* bk = (const float*)d_in[6];
    const float* Wv = (const float*)d_in[7];
    const float* bv = (const float*)d_in[8];
    const float* Wo = (const float*)d_in[9];
    const float* bo = (const float*)d_in[10];
    float* out = (float*)d_out;

    __half* hb = nullptr;
    cudaGetSymbolAddress((void**)&hb, g_h16);
    __half* AQ  = hb + HP_AQ;
    __half* AK  = hb + HP_AK;
    __half* AV  = hb + HP_AV;
    __half* AOp = hb + HP_AOP;
    __half* Wqp = hb + HP_W0;
    __half* Wkp = Wqp + HP_WSZ;
    __half* Wvp = Wkp + HP_WSZ;
    __half* Wop = Wvp + HP_WSZ;
    __half* QH  = hb + HP_QH;
    __half* KH  = hb + HP_KH;
    __half* VH  = hb + HP_VH;

    cudaFuncSetAttribute(hgemm_split_kernel,
                         cudaFuncAttributeMaxDynamicSharedMemorySize, GEMM_SMEM);
    cudaFuncSetAttribute(attn_h_kernel,
                         cudaFuncAttributeMaxDynamicSharedMemorySize, ATTN_SMEM);

    const int n4_in = M_ROWS * (KDIM / 4);
    const int n4_w  = MODEL * (KDIM / 4);
    cvt_split_kernel<<<n4_in / 256, 256>>>(query, AQ, n4_in);
    cvt_split_kernel<<<n4_in / 256, 256>>>(key_i, AK, n4_in);
    cvt_split_kernel<<<n4_in / 256, 256>>>(value, AV, n4_in);
    cvt_split_kernel<<<n4_w / 256, 256>>>(Wq, Wqp, n4_w);
    cvt_split_kernel<<<n4_w / 256, 256>>>(Wk, Wkp, n4_w);
    cvt_split_kernel<<<n4_w / 256, 256>>>(Wv, Wvp, n4_w);
    cvt_split_kernel<<<n4_w / 256, 256>>>(Wo, Wop, n4_w);

    dim3 gg(MODEL / 256, M_ROWS / 128);      // (4, 64)
    hgemm_split_kernel<<<gg, 256, GEMM_SMEM>>>(AQ, Wqp, bq, QH, 0, 0.125f);
    hgemm_split_kernel<<<gg, 256, GEMM_SMEM>>>(AK, Wkp, bk, KH, 0, 1.0f);
    hgemm_split_kernel<<<gg, 256, GEMM_SMEM>>>(AV, Wvp, bv, VH, 2, 1.0f);

    dim3 ga(NQB, B_SZ * NH);                 // (16, 64)
    attn_h_kernel<<<ga, 256, ATTN_SMEM>>>(QH, KH, VH, AOp);

    hgemm_split_kernel<<<gg, 256, GEMM_SMEM>>>(AOp, Wop, bo, out, 1, 1.0f);
}